// round 1
// baseline (speedup 1.0000x reference)
#include <cuda_runtime.h>
#include <math.h>

// Global accumulators (no device alloc allowed)
__device__ double g_score_sum;
__device__ double g_sq_sum;

__global__ void zero_accum_kernel() {
    g_score_sum = 0.0;
    g_sq_sum = 0.0;
}

__device__ __forceinline__ void accum_elem(float p, float t, float& s_score, float& s_sq) {
    float d = p - t;
    // diff<0 -> exp(-d/13)-1 ; diff>=0 -> exp(d/10)-1
    float arg = (d < 0.0f) ? (d * (-1.0f / 13.0f)) : (d * (1.0f / 10.0f));
    s_score += __expf(arg) - 1.0f;
    s_sq += d * d;
}

__global__ void __launch_bounds__(256) reduce_kernel(
    const float4* __restrict__ pred, const float4* __restrict__ tru, int n4)
{
    float s_score = 0.0f;
    float s_sq = 0.0f;

    int idx = blockIdx.x * blockDim.x + threadIdx.x;
    int stride = gridDim.x * blockDim.x;

    for (int i = idx; i < n4; i += stride) {
        float4 a = pred[i];
        float4 b = tru[i];
        accum_elem(a.x, b.x, s_score, s_sq);
        accum_elem(a.y, b.y, s_score, s_sq);
        accum_elem(a.z, b.z, s_score, s_sq);
        accum_elem(a.w, b.w, s_score, s_sq);
    }

    // Warp reduction
    #pragma unroll
    for (int off = 16; off > 0; off >>= 1) {
        s_score += __shfl_down_sync(0xFFFFFFFFu, s_score, off);
        s_sq    += __shfl_down_sync(0xFFFFFFFFu, s_sq, off);
    }

    // Block reduction in shared (double to preserve precision across blocks)
    __shared__ double sh_score[8];
    __shared__ double sh_sq[8];
    int wid = threadIdx.x >> 5;
    int lid = threadIdx.x & 31;
    if (lid == 0) {
        sh_score[wid] = (double)s_score;
        sh_sq[wid]    = (double)s_sq;
    }
    __syncthreads();

    if (threadIdx.x == 0) {
        double bs = 0.0, bq = 0.0;
        #pragma unroll
        for (int w = 0; w < 8; w++) { bs += sh_score[w]; bq += sh_sq[w]; }
        atomicAdd(&g_score_sum, bs);
        atomicAdd(&g_sq_sum, bq);
    }
}

__global__ void finalize_kernel(const float* __restrict__ theta_ptr,
                                float* __restrict__ out, float inv_n)
{
    double score = g_score_sum;
    double sq = g_sq_sum;
    float theta = theta_ptr[0];
    double rmse = sqrt(sq * (double)inv_n);
    out[0] = (float)((double)theta * score + (1.0 - (double)theta) * rmse);
}

extern "C" void kernel_launch(void* const* d_in, const int* in_sizes, int n_in,
                              void* d_out, int out_size) {
    const float* pred  = (const float*)d_in[0];
    const float* tru   = (const float*)d_in[1];
    const float* theta = (const float*)d_in[2];
    float* out = (float*)d_out;

    int n = in_sizes[0];           // 16777216
    int n4 = n >> 2;               // float4 count

    zero_accum_kernel<<<1, 1>>>();

    const int threads = 256;
    const int blocks = 148 * 8;    // 8 CTAs/SM, full chip, grid-stride covers rest
    reduce_kernel<<<blocks, threads>>>(
        (const float4*)pred, (const float4*)tru, n4);

    finalize_kernel<<<1, 1>>>(theta, out, 1.0f / (float)n);
}

// round 2
// speedup vs baseline: 1.0077x; 1.0077x over previous
#include <cuda_runtime.h>
#include <math.h>

// Fixed launch geometry
#define REDUCE_BLOCKS (148 * 8)   // 1184
#define REDUCE_THREADS 256

// Per-block partials: each block writes its own slot every call -> no zeroing
// kernel needed, fully deterministic, graph-capturable.
__device__ double2 g_partials[REDUCE_BLOCKS];

__device__ __forceinline__ void accum_elem(float p, float t, float& s_score, float& s_sq) {
    float d = p - t;
    // diff<0 -> exp(-d/13)-1 ; diff>=0 -> exp(d/10)-1
    float arg = (d < 0.0f) ? (d * (-1.0f / 13.0f)) : (d * (1.0f / 10.0f));
    s_score += __expf(arg) - 1.0f;
    s_sq += d * d;
}

__global__ void __launch_bounds__(REDUCE_THREADS) reduce_kernel(
    const float4* __restrict__ pred, const float4* __restrict__ tru, int n4)
{
    float s_score = 0.0f;
    float s_sq = 0.0f;

    int idx = blockIdx.x * blockDim.x + threadIdx.x;
    int stride = gridDim.x * blockDim.x;

    // Unrolled x2: 4 independent 128-bit streaming loads per iteration
    int i = idx;
    for (; i + stride < n4; i += 2 * stride) {
        float4 a0 = __ldcs(&pred[i]);
        float4 b0 = __ldcs(&tru[i]);
        float4 a1 = __ldcs(&pred[i + stride]);
        float4 b1 = __ldcs(&tru[i + stride]);
        accum_elem(a0.x, b0.x, s_score, s_sq);
        accum_elem(a0.y, b0.y, s_score, s_sq);
        accum_elem(a0.z, b0.z, s_score, s_sq);
        accum_elem(a0.w, b0.w, s_score, s_sq);
        accum_elem(a1.x, b1.x, s_score, s_sq);
        accum_elem(a1.y, b1.y, s_score, s_sq);
        accum_elem(a1.z, b1.z, s_score, s_sq);
        accum_elem(a1.w, b1.w, s_score, s_sq);
    }
    if (i < n4) {
        float4 a = __ldcs(&pred[i]);
        float4 b = __ldcs(&tru[i]);
        accum_elem(a.x, b.x, s_score, s_sq);
        accum_elem(a.y, b.y, s_score, s_sq);
        accum_elem(a.z, b.z, s_score, s_sq);
        accum_elem(a.w, b.w, s_score, s_sq);
    }

    // Warp reduction (fp32 within warp)
    #pragma unroll
    for (int off = 16; off > 0; off >>= 1) {
        s_score += __shfl_down_sync(0xFFFFFFFFu, s_score, off);
        s_sq    += __shfl_down_sync(0xFFFFFFFFu, s_sq, off);
    }

    // Block reduction in shared (double across warps)
    __shared__ double sh_score[REDUCE_THREADS / 32];
    __shared__ double sh_sq[REDUCE_THREADS / 32];
    int wid = threadIdx.x >> 5;
    int lid = threadIdx.x & 31;
    if (lid == 0) {
        sh_score[wid] = (double)s_score;
        sh_sq[wid]    = (double)s_sq;
    }
    __syncthreads();

    if (threadIdx.x == 0) {
        double bs = 0.0, bq = 0.0;
        #pragma unroll
        for (int w = 0; w < REDUCE_THREADS / 32; w++) { bs += sh_score[w]; bq += sh_sq[w]; }
        g_partials[blockIdx.x] = make_double2(bs, bq);
    }
}

__global__ void __launch_bounds__(256) finalize_kernel(
    const float* __restrict__ theta_ptr, float* __restrict__ out, float inv_n)
{
    double s_score = 0.0, s_sq = 0.0;
    for (int i = threadIdx.x; i < REDUCE_BLOCKS; i += 256) {
        double2 p = g_partials[i];
        s_score += p.x;
        s_sq    += p.y;
    }

    // Warp reduce (double via shfl on 64-bit)
    #pragma unroll
    for (int off = 16; off > 0; off >>= 1) {
        s_score += __shfl_down_sync(0xFFFFFFFFu, s_score, off);
        s_sq    += __shfl_down_sync(0xFFFFFFFFu, s_sq, off);
    }

    __shared__ double sh_score[8];
    __shared__ double sh_sq[8];
    int wid = threadIdx.x >> 5;
    int lid = threadIdx.x & 31;
    if (lid == 0) {
        sh_score[wid] = s_score;
        sh_sq[wid]    = s_sq;
    }
    __syncthreads();

    if (threadIdx.x == 0) {
        double score = 0.0, sq = 0.0;
        #pragma unroll
        for (int w = 0; w < 8; w++) { score += sh_score[w]; sq += sh_sq[w]; }
        float theta = theta_ptr[0];
        double rmse = sqrt(sq * (double)inv_n);
        out[0] = (float)((double)theta * score + (1.0 - (double)theta) * rmse);
    }
}

extern "C" void kernel_launch(void* const* d_in, const int* in_sizes, int n_in,
                              void* d_out, int out_size) {
    const float* pred  = (const float*)d_in[0];
    const float* tru   = (const float*)d_in[1];
    const float* theta = (const float*)d_in[2];
    float* out = (float*)d_out;

    int n = in_sizes[0];           // 16777216
    int n4 = n >> 2;               // float4 count

    reduce_kernel<<<REDUCE_BLOCKS, REDUCE_THREADS>>>(
        (const float4*)pred, (const float4*)tru, n4);

    finalize_kernel<<<1, 256>>>(theta, out, 1.0f / (float)n);
}